// round 13
// baseline (speedup 1.0000x reference)
#include <cuda_runtime.h>
#include <cstdint>

#define BETA 0.95f
#define MB 512
#define L1N 2048
#define L2N 2048
#define L3N 512
#define K1IN 1024
#define TSTEPS 16

#define NM2 (L2N * MB)
#define NM3 (L3N * MB)

// ---------------- scratch ----------------
__device__ float g_xT [K1IN * MB];             // xT [k][m]
__device__ float g_w1T[K1IN * L1N];            // W1T[k][n]
__device__ float g_w2T[L1N * L2N];             // W2T[k][n]
__device__ float g_w3T[L2N * L3N];             // W3T[k][n]
__device__ float g_s1 [TSTEPS * NM2];          // s1 [t][k][m]
__device__ float g_C2 [TSTEPS * NM2];          // C2 [t][n][m] (becomes s2 in-place)
__device__ float g_C3 [TSTEPS * NM3];          // C3 [t][n][m]

// packed f32x2: per-lane IEEE fp32 FMA (RN) -> bit-exact vs FFMA
#define FMA2(d, a, b) \
    asm("fma.rn.f32x2 %0, %1, %2, %0;" : "+l"(d) : "l"(a), "l"(b))
#define PACK2(d, x) \
    asm("mov.b64 %0, {%1, %1};" : "=l"(d) : "f"(x))
#define UNPACK2(lo, hi, v) \
    asm("mov.b64 {%0, %1}, %2;" : "=f"(lo), "=f"(hi) : "l"(v))

// ---------------- transpose ----------------
__global__ void transpose_k(const float* __restrict__ src, float* __restrict__ dst,
                            int R, int C) {
    __shared__ float t[32][33];
    const int c0 = blockIdx.x * 32, r0 = blockIdx.y * 32;
    for (int j = threadIdx.y; j < 32; j += 8)
        t[j][threadIdx.x] = src[(size_t)(r0 + j) * C + c0 + threadIdx.x];
    __syncthreads();
    for (int j = threadIdx.y; j < 32; j += 8)
        dst[(size_t)(c0 + j) * R + r0 + threadIdx.x] = t[threadIdx.x][j];
}

// ---------------- batched fp32x2 GEMM, persistent tiles (bit-exact ascending-k) ----------------
// Tile 128m x 64n, 256 threads, per-thread 8m (4 pairs) x 4n, BK=32, double-buffered smem,
// ping-pong fragment prefetch. A matrices are [K][512] per t-chunk.
// MODE 0: layer-1 fused epilogue: c = acc + bias[n]; 16-step LIF; spikes -> outp t-slices.
// MODE 1: raw store outp[tch][n*512+m] = acc (bias applied in recurrence kernels).
template <int MODE>
__global__ void __launch_bounds__(256, 2) gemmB(
    const float* __restrict__ A, size_t chunkA,
    const float* __restrict__ BT, int Ntot,
    const float* __restrict__ bias,
    float* __restrict__ outp, size_t chunkOut,
    int K, int nbx, int ntiles)
{
    __shared__ __align__(16) float As[2 * 32 * 128];   // 32 KB
    __shared__ __align__(16) float Bs[2 * 32 * 64];    // 16 KB

    const int tid = threadIdx.x;
    const int akk = tid >> 5;            // + i*8   (A: 32 k x 128 m)
    const int amq = (tid & 31) * 4;
    const int bkk = tid >> 4;            // + i*16  (B: 32 k x 64 n)
    const int bnq = (tid & 15) * 4;
    const int tx  = tid & 15;            // n: 4 cols
    const int ty  = tid >> 4;            // m: 8 rows (4 packed pairs)

    for (int tile = blockIdx.x; tile < ntiles; tile += gridDim.x) {
        const int m0 = (tile / nbx) * 128;
        const int n0 = (tile % nbx) * 64;
        const int tch = m0 >> 9;
        const int mloc = m0 & 511;
        const float* Ab = A + (size_t)tch * chunkA + mloc;

        uint64_t acc2[4][4];
#pragma unroll
        for (int i = 0; i < 4; i++)
#pragma unroll
            for (int j = 0; j < 4; j++) acc2[i][j] = 0ull;

        float4 pa[4], pb[2];
        const int niter = K >> 5;

        // prologue: tile 0 -> regs -> buffer 0
#pragma unroll
        for (int i = 0; i < 4; i++)
            pa[i] = *reinterpret_cast<const float4*>(Ab + (size_t)(akk + i * 8) * 512 + amq);
#pragma unroll
        for (int i = 0; i < 2; i++)
            pb[i] = *reinterpret_cast<const float4*>(BT + (size_t)(bkk + i * 16) * Ntot + n0 + bnq);
#pragma unroll
        for (int i = 0; i < 4; i++)
            *reinterpret_cast<float4*>(As + (akk + i * 8) * 128 + amq) = pa[i];
#pragma unroll
        for (int i = 0; i < 2; i++)
            *reinterpret_cast<float4*>(Bs + (bkk + i * 16) * 64 + bnq) = pb[i];

        for (int it = 0; it < niter; it++) {
            const int b = it & 1;
            __syncthreads();   // buffer b filled; prior readers of b^1 (or prior tile) done

            const bool more = (it + 1 < niter);
            if (more) {
                const int k0 = (it + 1) * 32;
#pragma unroll
                for (int i = 0; i < 4; i++)
                    pa[i] = *reinterpret_cast<const float4*>(Ab + (size_t)(k0 + akk + i * 8) * 512 + amq);
#pragma unroll
                for (int i = 0; i < 2; i++)
                    pb[i] = *reinterpret_cast<const float4*>(BT + (size_t)(k0 + bkk + i * 16) * Ntot + n0 + bnq);
            }

            float* Abuf = As + b * (32 * 128);
            float* Bbuf = Bs + b * (32 * 64);

            // ping-pong fragment prefetch across k
            ulonglong2 fa[2], fa2[2];
            float4 fw[2];
            fa [0] = *reinterpret_cast<const ulonglong2*>(Abuf + ty * 8);
            fa2[0] = *reinterpret_cast<const ulonglong2*>(Abuf + ty * 8 + 4);
            fw [0] = *reinterpret_cast<const float4*>(Bbuf + tx * 4);
#pragma unroll
            for (int k = 0; k < 32; k++) {
                const int cur = k & 1, nxt = cur ^ 1;
                if (k < 31) {
                    fa [nxt] = *reinterpret_cast<const ulonglong2*>(Abuf + (k + 1) * 128 + ty * 8);
                    fa2[nxt] = *reinterpret_cast<const ulonglong2*>(Abuf + (k + 1) * 128 + ty * 8 + 4);
                    fw [nxt] = *reinterpret_cast<const float4*>(Bbuf + (k + 1) * 64 + tx * 4);
                }
                uint64_t br0, br1, br2, br3;
                PACK2(br0, fw[cur].x);
                PACK2(br1, fw[cur].y);
                PACK2(br2, fw[cur].z);
                PACK2(br3, fw[cur].w);
                FMA2(acc2[0][0], fa[cur].x, br0);  FMA2(acc2[0][1], fa[cur].x, br1);
                FMA2(acc2[0][2], fa[cur].x, br2);  FMA2(acc2[0][3], fa[cur].x, br3);
                FMA2(acc2[1][0], fa[cur].y, br0);  FMA2(acc2[1][1], fa[cur].y, br1);
                FMA2(acc2[1][2], fa[cur].y, br2);  FMA2(acc2[1][3], fa[cur].y, br3);
                FMA2(acc2[2][0], fa2[cur].x, br0); FMA2(acc2[2][1], fa2[cur].x, br1);
                FMA2(acc2[2][2], fa2[cur].x, br2); FMA2(acc2[2][3], fa2[cur].x, br3);
                FMA2(acc2[3][0], fa2[cur].y, br0); FMA2(acc2[3][1], fa2[cur].y, br1);
                FMA2(acc2[3][2], fa2[cur].y, br2); FMA2(acc2[3][3], fa2[cur].y, br3);
            }

            if (more) {
                const int nb = b ^ 1;
                float* Ad = As + nb * (32 * 128);
                float* Bd = Bs + nb * (32 * 64);
#pragma unroll
                for (int i = 0; i < 4; i++)
                    *reinterpret_cast<float4*>(Ad + (akk + i * 8) * 128 + amq) = pa[i];
#pragma unroll
                for (int i = 0; i < 2; i++)
                    *reinterpret_cast<float4*>(Bd + (bkk + i * 16) * 64 + bnq) = pb[i];
            }
        }

        // ---- epilogue ----
#pragma unroll
        for (int j = 0; j < 4; j++) {
            const int n = n0 + tx * 4 + j;
            float vv[8];
            UNPACK2(vv[0], vv[1], acc2[0][j]);
            UNPACK2(vv[2], vv[3], acc2[1][j]);
            UNPACK2(vv[4], vv[5], acc2[2][j]);
            UNPACK2(vv[6], vv[7], acc2[3][j]);
            if (MODE == 0) {
                // layer-1 fused: c = acc + bias; 16-step LIF; write spike slices
                const float bj = bias[n];
                float c[8], mm[8];
#pragma unroll
                for (int h = 0; h < 8; h++) { c[h] = vv[h] + bj; mm[h] = 0.0f; }
                float* dst0 = outp + (size_t)n * 512 + mloc + ty * 8;
#pragma unroll
                for (int t = 0; t < TSTEPS; t++) {
                    float s[8];
#pragma unroll
                    for (int h = 0; h < 8; h++) {
                        float m2 = BETA * mm[h] + c[h];
                        s[h] = (m2 > 1.0f) ? 1.0f : 0.0f;
                        mm[h] = m2 - s[h];
                    }
                    float4 o0, o1;
                    o0.x = s[0]; o0.y = s[1]; o0.z = s[2]; o0.w = s[3];
                    o1.x = s[4]; o1.y = s[5]; o1.z = s[6]; o1.w = s[7];
                    float* dst = dst0 + (size_t)t * NM2;
                    *reinterpret_cast<float4*>(dst) = o0;
                    *reinterpret_cast<float4*>(dst + 4) = o1;
                }
            } else {
                float* dst = outp + (size_t)tch * chunkOut + (size_t)n * 512 + mloc + ty * 8;
                float4 o0, o1;
                o0.x = vv[0]; o0.y = vv[1]; o0.z = vv[2]; o0.w = vv[3];
                o1.x = vv[4]; o1.y = vv[5]; o1.z = vv[6]; o1.w = vv[7];
                *reinterpret_cast<float4*>(dst) = o0;
                *reinterpret_cast<float4*>(dst + 4) = o1;
            }
        }
    }
}

// ---- layer-2 recurrence: membranes in registers, spikes in-place over C2 ----
__global__ void rec2(const float* __restrict__ b2) {
    int i = blockIdx.x * blockDim.x + threadIdx.x;
    const float bj = b2[i >> 9];
    float mm = 0.0f;
#pragma unroll
    for (int t = 0; t < TSTEPS; t++) {
        float c = g_C2[t * NM2 + i];
        float v = c + bj;
        float m2 = BETA * mm + v;
        float s = (m2 > 1.0f) ? 1.0f : 0.0f;
        mm = m2 - s;
        g_C2[t * NM2 + i] = s;
    }
}

// ---- layer-3 recurrence + output sum ----
__global__ void rec3(const float* __restrict__ b3, float* __restrict__ out) {
    int i = blockIdx.x * blockDim.x + threadIdx.x;
    const int n = i >> 9, m = i & 511;
    const float bj = b3[n];
    float mm = 0.0f, sum = 0.0f;
#pragma unroll
    for (int t = 0; t < TSTEPS; t++) {
        float c = g_C3[t * NM3 + i];
        float v = c + bj;
        float m3 = BETA * mm + v;
        float s = (m3 > 1.0f) ? 1.0f : 0.0f;
        mm = m3 - s;
        sum += s;
    }
    out[(size_t)m * L3N + n] = sum;
}

// ---------------- host ----------------
extern "C" void kernel_launch(void* const* d_in, const int* in_sizes, int n_in,
                              void* d_out, int out_size)
{
    const float* x  = (const float*)d_in[0];
    const float* W1 = (const float*)d_in[1];
    const float* b1 = (const float*)d_in[2];
    const float* W2 = (const float*)d_in[3];
    const float* b2 = (const float*)d_in[4];
    const float* W3 = (const float*)d_in[5];
    const float* b3 = (const float*)d_in[6];
    float* out = (float*)d_out;

    float *xT, *w1T, *w2T, *w3T, *s1, *C2, *C3;
    cudaGetSymbolAddress((void**)&xT,  g_xT);
    cudaGetSymbolAddress((void**)&w1T, g_w1T);
    cudaGetSymbolAddress((void**)&w2T, g_w2T);
    cudaGetSymbolAddress((void**)&w3T, g_w3T);
    cudaGetSymbolAddress((void**)&s1,  g_s1);
    cudaGetSymbolAddress((void**)&C2,  g_C2);
    cudaGetSymbolAddress((void**)&C3,  g_C3);

    dim3 tb(32, 8);
    transpose_k<<<dim3(K1IN / 32, MB  / 32), tb>>>(x,  xT,  MB,  K1IN);
    transpose_k<<<dim3(K1IN / 32, L1N / 32), tb>>>(W1, w1T, L1N, K1IN);
    transpose_k<<<dim3(L1N  / 32, L2N / 32), tb>>>(W2, w2T, L2N, L1N);
    transpose_k<<<dim3(L2N  / 32, L3N / 32), tb>>>(W3, w3T, L3N, L2N);

    // layer-1 GEMM + fused 16-step LIF -> s1   (128 tiles, 1 per CTA)
    gemmB<0><<<128, 256>>>(xT, 0, w1T, L1N, b1, s1, 0, K1IN, 32, 128);

    // batched layer-2 GEMM: C2[t] = s1[t] @ W2^T  (2048 tiles, persistent grid 296)
    gemmB<1><<<296, 256>>>(s1, (size_t)NM2, w2T, L2N, nullptr,
                           C2, (size_t)NM2, L1N, 32, 2048);

    // layer-2 membrane recurrence, spikes in-place
    rec2<<<NM2 / 256, 256>>>(b2);

    // batched layer-3 GEMM: C3[t] = s2[t] @ W3^T  (512 tiles, grid 256 -> 2 each)
    gemmB<1><<<256, 256>>>(C2, (size_t)NM2, w3T, L3N, nullptr,
                           C3, (size_t)NM3, L2N, 8, 512);

    // layer-3 recurrence + spike-count sum -> out
    rec3<<<NM3 / 256, 256>>>(b3, out);
}

// round 14
// speedup vs baseline: 1.0051x; 1.0051x over previous
#include <cuda_runtime.h>
#include <cstdint>

#define BETA 0.95f
#define MB 512
#define L1N 2048
#define L2N 2048
#define L3N 512
#define K1IN 1024
#define TSTEPS 16

#define NM2 (L2N * MB)
#define NM3 (L3N * MB)

// ---------------- scratch ----------------
__device__ float g_xT [K1IN * MB];             // xT [k][m]
__device__ float g_w1T[K1IN * L1N];            // W1T[k][n]
__device__ float g_w2T[L1N * L2N];             // W2T[k][n]
__device__ float g_w3T[L2N * L3N];             // W3T[k][n]
__device__ float g_s1 [TSTEPS * NM2];          // s1 [t][k][m]
__device__ float g_C2 [TSTEPS * NM2];          // C2 [t][n][m] (becomes s2 in-place)
__device__ float g_C3 [TSTEPS * NM3];          // C3 [t][n][m]

// packed f32x2: per-lane IEEE fp32 FMA (RN) -> bit-exact vs FFMA
#define FMA2(d, a, b) \
    asm("fma.rn.f32x2 %0, %1, %2, %0;" : "+l"(d) : "l"(a), "l"(b))
#define PACK2(d, x) \
    asm("mov.b64 %0, {%1, %1};" : "=l"(d) : "f"(x))
#define UNPACK2(lo, hi, v) \
    asm("mov.b64 {%0, %1}, %2;" : "=f"(lo), "=f"(hi) : "l"(v))

// ---------------- transpose ----------------
__global__ void transpose_k(const float* __restrict__ src, float* __restrict__ dst,
                            int R, int C) {
    __shared__ float t[32][33];
    const int c0 = blockIdx.x * 32, r0 = blockIdx.y * 32;
    for (int j = threadIdx.y; j < 32; j += 8)
        t[j][threadIdx.x] = src[(size_t)(r0 + j) * C + c0 + threadIdx.x];
    __syncthreads();
    for (int j = threadIdx.y; j < 32; j += 8)
        dst[(size_t)(c0 + j) * R + r0 + threadIdx.x] = t[threadIdx.x][j];
}

// ---------------- batched fp32x2 GEMM, persistent tiles (bit-exact ascending-k) ----------------
// Tile 128m x 64n, 256 threads, per-thread 8m (4 pairs) x 4n, BK=32, double-buffered smem.
// Plain per-k fragment loads (R12 style; ptxas schedules). A matrices are [K][512] per t-chunk.
// MODE 0: layer-1 fused epilogue: c = acc + bias[n]; 16-step LIF; spikes -> outp t-slices.
// MODE 1: raw store outp[tch][n*512+m] = acc (bias applied in recurrence kernels).
template <int MODE>
__global__ void __launch_bounds__(256, 2) gemmB(
    const float* __restrict__ A, size_t chunkA,
    const float* __restrict__ BT, int Ntot,
    const float* __restrict__ bias,
    float* __restrict__ outp, size_t chunkOut,
    int K, int nbx, int ntiles)
{
    __shared__ __align__(16) float As[2 * 32 * 128];   // 32 KB
    __shared__ __align__(16) float Bs[2 * 32 * 64];    // 16 KB

    const int tid = threadIdx.x;
    const int akk = tid >> 5;            // + i*8   (A: 32 k x 128 m)
    const int amq = (tid & 31) * 4;
    const int bkk = tid >> 4;            // + i*16  (B: 32 k x 64 n)
    const int bnq = (tid & 15) * 4;
    const int tx  = tid & 15;            // n: 4 cols
    const int ty  = tid >> 4;            // m: 8 rows (4 packed pairs)

    for (int tile = blockIdx.x; tile < ntiles; tile += gridDim.x) {
        const int m0 = (tile / nbx) * 128;
        const int n0 = (tile % nbx) * 64;
        const int tch = m0 >> 9;
        const int mloc = m0 & 511;
        const float* Ab = A + (size_t)tch * chunkA + mloc;

        uint64_t acc2[4][4];
#pragma unroll
        for (int i = 0; i < 4; i++)
#pragma unroll
            for (int j = 0; j < 4; j++) acc2[i][j] = 0ull;

        float4 pa[4], pb[2];
        const int niter = K >> 5;

        // prologue: tile 0 -> regs -> buffer 0
#pragma unroll
        for (int i = 0; i < 4; i++)
            pa[i] = *reinterpret_cast<const float4*>(Ab + (size_t)(akk + i * 8) * 512 + amq);
#pragma unroll
        for (int i = 0; i < 2; i++)
            pb[i] = *reinterpret_cast<const float4*>(BT + (size_t)(bkk + i * 16) * Ntot + n0 + bnq);
#pragma unroll
        for (int i = 0; i < 4; i++)
            *reinterpret_cast<float4*>(As + (akk + i * 8) * 128 + amq) = pa[i];
#pragma unroll
        for (int i = 0; i < 2; i++)
            *reinterpret_cast<float4*>(Bs + (bkk + i * 16) * 64 + bnq) = pb[i];

        for (int it = 0; it < niter; it++) {
            const int b = it & 1;
            __syncthreads();   // buffer b filled; prior readers of b^1 (or prior tile) done

            const bool more = (it + 1 < niter);
            if (more) {
                const int k0 = (it + 1) * 32;
#pragma unroll
                for (int i = 0; i < 4; i++)
                    pa[i] = *reinterpret_cast<const float4*>(Ab + (size_t)(k0 + akk + i * 8) * 512 + amq);
#pragma unroll
                for (int i = 0; i < 2; i++)
                    pb[i] = *reinterpret_cast<const float4*>(BT + (size_t)(k0 + bkk + i * 16) * Ntot + n0 + bnq);
            }

            float* Abuf = As + b * (32 * 128);
            float* Bbuf = Bs + b * (32 * 64);
#pragma unroll
            for (int k = 0; k < 32; k++) {
                ulonglong2 a01 = *reinterpret_cast<const ulonglong2*>(Abuf + k * 128 + ty * 8);
                ulonglong2 a23 = *reinterpret_cast<const ulonglong2*>(Abuf + k * 128 + ty * 8 + 4);
                float4 w = *reinterpret_cast<const float4*>(Bbuf + k * 64 + tx * 4);
                uint64_t br0, br1, br2, br3;
                PACK2(br0, w.x);
                PACK2(br1, w.y);
                PACK2(br2, w.z);
                PACK2(br3, w.w);
                FMA2(acc2[0][0], a01.x, br0); FMA2(acc2[0][1], a01.x, br1);
                FMA2(acc2[0][2], a01.x, br2); FMA2(acc2[0][3], a01.x, br3);
                FMA2(acc2[1][0], a01.y, br0); FMA2(acc2[1][1], a01.y, br1);
                FMA2(acc2[1][2], a01.y, br2); FMA2(acc2[1][3], a01.y, br3);
                FMA2(acc2[2][0], a23.x, br0); FMA2(acc2[2][1], a23.x, br1);
                FMA2(acc2[2][2], a23.x, br2); FMA2(acc2[2][3], a23.x, br3);
                FMA2(acc2[3][0], a23.y, br0); FMA2(acc2[3][1], a23.y, br1);
                FMA2(acc2[3][2], a23.y, br2); FMA2(acc2[3][3], a23.y, br3);
            }

            if (more) {
                const int nb = b ^ 1;
                float* Ad = As + nb * (32 * 128);
                float* Bd = Bs + nb * (32 * 64);
#pragma unroll
                for (int i = 0; i < 4; i++)
                    *reinterpret_cast<float4*>(Ad + (akk + i * 8) * 128 + amq) = pa[i];
#pragma unroll
                for (int i = 0; i < 2; i++)
                    *reinterpret_cast<float4*>(Bd + (bkk + i * 16) * 64 + bnq) = pb[i];
            }
        }

        // ---- epilogue ----
#pragma unroll
        for (int j = 0; j < 4; j++) {
            const int n = n0 + tx * 4 + j;
            float vv[8];
            UNPACK2(vv[0], vv[1], acc2[0][j]);
            UNPACK2(vv[2], vv[3], acc2[1][j]);
            UNPACK2(vv[4], vv[5], acc2[2][j]);
            UNPACK2(vv[6], vv[7], acc2[3][j]);
            if (MODE == 0) {
                // layer-1 fused: c = acc + bias; 16-step LIF; write spike slices
                const float bj = bias[n];
                float c[8], mm[8];
#pragma unroll
                for (int h = 0; h < 8; h++) { c[h] = vv[h] + bj; mm[h] = 0.0f; }
                float* dst0 = outp + (size_t)n * 512 + mloc + ty * 8;
#pragma unroll
                for (int t = 0; t < TSTEPS; t++) {
                    float s[8];
#pragma unroll
                    for (int h = 0; h < 8; h++) {
                        float m2 = BETA * mm[h] + c[h];
                        s[h] = (m2 > 1.0f) ? 1.0f : 0.0f;
                        mm[h] = m2 - s[h];
                    }
                    float4 o0, o1;
                    o0.x = s[0]; o0.y = s[1]; o0.z = s[2]; o0.w = s[3];
                    o1.x = s[4]; o1.y = s[5]; o1.z = s[6]; o1.w = s[7];
                    float* dst = dst0 + (size_t)t * NM2;
                    *reinterpret_cast<float4*>(dst) = o0;
                    *reinterpret_cast<float4*>(dst + 4) = o1;
                }
            } else {
                float* dst = outp + (size_t)tch * chunkOut + (size_t)n * 512 + mloc + ty * 8;
                float4 o0, o1;
                o0.x = vv[0]; o0.y = vv[1]; o0.z = vv[2]; o0.w = vv[3];
                o1.x = vv[4]; o1.y = vv[5]; o1.z = vv[6]; o1.w = vv[7];
                *reinterpret_cast<float4*>(dst) = o0;
                *reinterpret_cast<float4*>(dst + 4) = o1;
            }
        }
    }
}

// ---- layer-2 recurrence: membranes in registers, spikes in-place over C2 ----
__global__ void rec2(const float* __restrict__ b2) {
    int i = blockIdx.x * blockDim.x + threadIdx.x;
    const float bj = b2[i >> 9];
    float mm = 0.0f;
#pragma unroll
    for (int t = 0; t < TSTEPS; t++) {
        float c = g_C2[t * NM2 + i];
        float v = c + bj;
        float m2 = BETA * mm + v;
        float s = (m2 > 1.0f) ? 1.0f : 0.0f;
        mm = m2 - s;
        g_C2[t * NM2 + i] = s;
    }
}

// ---- layer-3 recurrence + output sum ----
__global__ void rec3(const float* __restrict__ b3, float* __restrict__ out) {
    int i = blockIdx.x * blockDim.x + threadIdx.x;
    const int n = i >> 9, m = i & 511;
    const float bj = b3[n];
    float mm = 0.0f, sum = 0.0f;
#pragma unroll
    for (int t = 0; t < TSTEPS; t++) {
        float c = g_C3[t * NM3 + i];
        float v = c + bj;
        float m3 = BETA * mm + v;
        float s = (m3 > 1.0f) ? 1.0f : 0.0f;
        mm = m3 - s;
        sum += s;
    }
    out[(size_t)m * L3N + n] = sum;
}

// ---------------- host ----------------
extern "C" void kernel_launch(void* const* d_in, const int* in_sizes, int n_in,
                              void* d_out, int out_size)
{
    const float* x  = (const float*)d_in[0];
    const float* W1 = (const float*)d_in[1];
    const float* b1 = (const float*)d_in[2];
    const float* W2 = (const float*)d_in[3];
    const float* b2 = (const float*)d_in[4];
    const float* W3 = (const float*)d_in[5];
    const float* b3 = (const float*)d_in[6];
    float* out = (float*)d_out;

    float *xT, *w1T, *w2T, *w3T, *s1, *C2, *C3;
    cudaGetSymbolAddress((void**)&xT,  g_xT);
    cudaGetSymbolAddress((void**)&w1T, g_w1T);
    cudaGetSymbolAddress((void**)&w2T, g_w2T);
    cudaGetSymbolAddress((void**)&w3T, g_w3T);
    cudaGetSymbolAddress((void**)&s1,  g_s1);
    cudaGetSymbolAddress((void**)&C2,  g_C2);
    cudaGetSymbolAddress((void**)&C3,  g_C3);

    dim3 tb(32, 8);
    transpose_k<<<dim3(K1IN / 32, MB  / 32), tb>>>(x,  xT,  MB,  K1IN);
    transpose_k<<<dim3(K1IN / 32, L1N / 32), tb>>>(W1, w1T, L1N, K1IN);
    transpose_k<<<dim3(L1N  / 32, L2N / 32), tb>>>(W2, w2T, L2N, L1N);
    transpose_k<<<dim3(L2N  / 32, L3N / 32), tb>>>(W3, w3T, L3N, L2N);

    // layer-1 GEMM + fused 16-step LIF -> s1   (128 tiles, 1 per CTA)
    gemmB<0><<<128, 256>>>(xT, 0, w1T, L1N, b1, s1, 0, K1IN, 32, 128);

    // batched layer-2 GEMM: C2[t] = s1[t] @ W2^T  (2048 tiles, persistent grid 296)
    gemmB<1><<<296, 256>>>(s1, (size_t)NM2, w2T, L2N, nullptr,
                           C2, (size_t)NM2, L1N, 32, 2048);

    // layer-2 membrane recurrence, spikes in-place
    rec2<<<NM2 / 256, 256>>>(b2);

    // batched layer-3 GEMM: C3[t] = s2[t] @ W3^T  (512 tiles, grid 256 -> 2 each)
    gemmB<1><<<256, 256>>>(C2, (size_t)NM2, w3T, L3N, nullptr,
                           C3, (size_t)NM3, L2N, 8, 512);

    // layer-3 recurrence + spike-count sum -> out
    rec3<<<NM3 / 256, 256>>>(b3, out);
}

// round 16
// speedup vs baseline: 1.0544x; 1.0491x over previous
#include <cuda_runtime.h>
#include <cstdint>

#define BETA 0.95f
#define MB 512
#define L1N 2048
#define L2N 2048
#define L3N 512
#define K1IN 1024
#define TSTEPS 16

#define NM2 (L2N * MB)
#define NM3 (L3N * MB)

// ---------------- scratch ----------------
__device__ float g_xT [K1IN * MB];             // xT [k][m]
__device__ float g_w1T[K1IN * L1N];            // W1T[k][n]
__device__ float g_w2T[L1N * L2N];             // W2T[k][n]
__device__ float g_w3T[L2N * L3N];             // W3T[k][n]
__device__ float g_c1T[L1N * MB];              // c1T[n][m]
__device__ float g_s1 [TSTEPS * NM2];          // s1 [t][k][m]
__device__ float g_C2 [TSTEPS * NM2];          // C2 [t][n][m] (becomes s2 in-place)
__device__ float g_C3 [TSTEPS * NM3];          // C3 [t][n][m]

// packed f32x2: per-lane IEEE fp32 FMA (RN) -> bit-exact vs FFMA
#define FMA2(d, a, b) \
    asm("fma.rn.f32x2 %0, %1, %2, %0;" : "+l"(d) : "l"(a), "l"(b))
#define PACK2(d, x) \
    asm("mov.b64 %0, {%1, %1};" : "=l"(d) : "f"(x))
#define UNPACK2(lo, hi, v) \
    asm("mov.b64 {%0, %1}, %2;" : "=f"(lo), "=f"(hi) : "l"(v))

// ---------------- transpose ----------------
__global__ void transpose_k(const float* __restrict__ src, float* __restrict__ dst,
                            int R, int C) {
    __shared__ float t[32][33];
    const int c0 = blockIdx.x * 32, r0 = blockIdx.y * 32;
    for (int j = threadIdx.y; j < 32; j += 8)
        t[j][threadIdx.x] = src[(size_t)(r0 + j) * C + c0 + threadIdx.x];
    __syncthreads();
    for (int j = threadIdx.y; j < 32; j += 8)
        dst[(size_t)(c0 + j) * R + r0 + threadIdx.x] = t[threadIdx.x][j];
}

// ---- layer-1: closed-form 16-step LIF on static current ----
__global__ void sim_layer1() {
    int i = blockIdx.x * blockDim.x + threadIdx.x;   // over c1T [n][m]
    float c = g_c1T[i];
    float m = 0.0f;
#pragma unroll
    for (int t = 0; t < TSTEPS; t++) {
        m = BETA * m + c;
        float s = (m > 1.0f) ? 1.0f : 0.0f;
        m -= s;
        g_s1[t * NM2 + i] = s;
    }
}

// ---------------- batched fp32x2 GEMM (bit-exact ascending-k), R12 inner loop ----------------
// Tile 128m x 64n, 256 threads, per-thread 8m (4 pairs) x 4n, BK=32, double-buffered.
// A matrices are [K][512] per t-chunk; tiles walked with optional grid-stride loop.
// MODE 0: out[tch][n*512+m] = acc + bias[n]
// MODE 1: out[tch][n*512+m] = acc          (bias applied in recurrence kernels)
template <int MODE>
__global__ void __launch_bounds__(256, 2) gemmB(
    const float* __restrict__ A, size_t chunkA,
    const float* __restrict__ BT, int Ntot,
    const float* __restrict__ bias,
    float* __restrict__ outp, size_t chunkOut,
    int K, int nbx, int ntiles)
{
    __shared__ __align__(16) float As[2 * 32 * 128];   // 32 KB
    __shared__ __align__(16) float Bs[2 * 32 * 64];    // 16 KB

    const int tid = threadIdx.x;
    const int akk = tid >> 5;            // + i*8   (A: 32 k x 128 m)
    const int amq = (tid & 31) * 4;
    const int bkk = tid >> 4;            // + i*16  (B: 32 k x 64 n)
    const int bnq = (tid & 15) * 4;
    const int tx  = tid & 15;            // n: 4 cols
    const int ty  = tid >> 4;            // m: 8 rows (4 packed pairs)

    for (int tile = blockIdx.x; tile < ntiles; tile += gridDim.x) {
        const int m0 = (tile / nbx) * 128;
        const int n0 = (tile % nbx) * 64;
        const int tch = m0 >> 9;
        const int mloc = m0 & 511;
        const float* Ab = A + (size_t)tch * chunkA + mloc;
        float* Ob = outp + (size_t)tch * chunkOut + mloc;

        uint64_t acc2[4][4];
#pragma unroll
        for (int i = 0; i < 4; i++)
#pragma unroll
            for (int j = 0; j < 4; j++) acc2[i][j] = 0ull;

        float4 pa[4], pb[2];
        const int niter = K >> 5;

        // prologue: tile 0 -> regs -> buffer 0
#pragma unroll
        for (int i = 0; i < 4; i++)
            pa[i] = *reinterpret_cast<const float4*>(Ab + (size_t)(akk + i * 8) * 512 + amq);
#pragma unroll
        for (int i = 0; i < 2; i++)
            pb[i] = *reinterpret_cast<const float4*>(BT + (size_t)(bkk + i * 16) * Ntot + n0 + bnq);
#pragma unroll
        for (int i = 0; i < 4; i++)
            *reinterpret_cast<float4*>(As + (akk + i * 8) * 128 + amq) = pa[i];
#pragma unroll
        for (int i = 0; i < 2; i++)
            *reinterpret_cast<float4*>(Bs + (bkk + i * 16) * 64 + bnq) = pb[i];

        for (int it = 0; it < niter; it++) {
            const int b = it & 1;
            __syncthreads();

            const bool more = (it + 1 < niter);
            if (more) {
                const int k0 = (it + 1) * 32;
#pragma unroll
                for (int i = 0; i < 4; i++)
                    pa[i] = *reinterpret_cast<const float4*>(Ab + (size_t)(k0 + akk + i * 8) * 512 + amq);
#pragma unroll
                for (int i = 0; i < 2; i++)
                    pb[i] = *reinterpret_cast<const float4*>(BT + (size_t)(k0 + bkk + i * 16) * Ntot + n0 + bnq);
            }

            float* Abuf = As + b * (32 * 128);
            float* Bbuf = Bs + b * (32 * 64);
#pragma unroll
            for (int k = 0; k < 32; k++) {
                ulonglong2 a01 = *reinterpret_cast<const ulonglong2*>(Abuf + k * 128 + ty * 8);
                ulonglong2 a23 = *reinterpret_cast<const ulonglong2*>(Abuf + k * 128 + ty * 8 + 4);
                float4 w = *reinterpret_cast<const float4*>(Bbuf + k * 64 + tx * 4);
                uint64_t br0, br1, br2, br3;
                PACK2(br0, w.x);
                PACK2(br1, w.y);
                PACK2(br2, w.z);
                PACK2(br3, w.w);
                FMA2(acc2[0][0], a01.x, br0); FMA2(acc2[0][1], a01.x, br1);
                FMA2(acc2[0][2], a01.x, br2); FMA2(acc2[0][3], a01.x, br3);
                FMA2(acc2[1][0], a01.y, br0); FMA2(acc2[1][1], a01.y, br1);
                FMA2(acc2[1][2], a01.y, br2); FMA2(acc2[1][3], a01.y, br3);
                FMA2(acc2[2][0], a23.x, br0); FMA2(acc2[2][1], a23.x, br1);
                FMA2(acc2[2][2], a23.x, br2); FMA2(acc2[2][3], a23.x, br3);
                FMA2(acc2[3][0], a23.y, br0); FMA2(acc2[3][1], a23.y, br1);
                FMA2(acc2[3][2], a23.y, br2); FMA2(acc2[3][3], a23.y, br3);
            }

            if (more) {
                const int nb = b ^ 1;
                float* Ad = As + nb * (32 * 128);
                float* Bd = Bs + nb * (32 * 64);
#pragma unroll
                for (int i = 0; i < 4; i++)
                    *reinterpret_cast<float4*>(Ad + (akk + i * 8) * 128 + amq) = pa[i];
#pragma unroll
                for (int i = 0; i < 2; i++)
                    *reinterpret_cast<float4*>(Bd + (bkk + i * 16) * 64 + bnq) = pb[i];
            }
        }

        // ---- epilogue ----
#pragma unroll
        for (int j = 0; j < 4; j++) {
            const int n = n0 + tx * 4 + j;
            float vv[8];
            UNPACK2(vv[0], vv[1], acc2[0][j]);
            UNPACK2(vv[2], vv[3], acc2[1][j]);
            UNPACK2(vv[4], vv[5], acc2[2][j]);
            UNPACK2(vv[6], vv[7], acc2[3][j]);
            if (MODE == 0) {
                const float bj = bias[n];
#pragma unroll
                for (int h = 0; h < 8; h++) vv[h] += bj;
            }
            float* dst = Ob + (size_t)n * 512 + ty * 8;
            float4 o0, o1;
            o0.x = vv[0]; o0.y = vv[1]; o0.z = vv[2]; o0.w = vv[3];
            o1.x = vv[4]; o1.y = vv[5]; o1.z = vv[6]; o1.w = vv[7];
            *reinterpret_cast<float4*>(dst) = o0;
            *reinterpret_cast<float4*>(dst + 4) = o1;
        }
    }
}

// ---- layer-2 recurrence (float4): membranes in registers, spikes in-place ----
__global__ void rec2(const float* __restrict__ b2) {
    int i4 = blockIdx.x * blockDim.x + threadIdx.x;   // float4 index over [n][m]
    const int base = i4 * 4;
    const float bj = b2[base >> 9];                   // 512 % 4 == 0 -> same n for all 4
    float mm[4] = {0.0f, 0.0f, 0.0f, 0.0f};
    float4* C2v = reinterpret_cast<float4*>(g_C2);
#pragma unroll
    for (int t = 0; t < TSTEPS; t++) {
        float4 c = C2v[t * (NM2 / 4) + i4];
        float cv[4] = { c.x, c.y, c.z, c.w };
        float sv[4];
#pragma unroll
        for (int h = 0; h < 4; h++) {
            float v = cv[h] + bj;
            float m2 = BETA * mm[h] + v;
            float s = (m2 > 1.0f) ? 1.0f : 0.0f;
            mm[h] = m2 - s;
            sv[h] = s;
        }
        float4 o; o.x = sv[0]; o.y = sv[1]; o.z = sv[2]; o.w = sv[3];
        C2v[t * (NM2 / 4) + i4] = o;
    }
}

// ---- layer-3 recurrence + output sum (float4 loads) ----
__global__ void rec3(const float* __restrict__ b3, float* __restrict__ out) {
    int i4 = blockIdx.x * blockDim.x + threadIdx.x;   // float4 index over [n][m]
    const int base = i4 * 4;
    const int n = base >> 9, m = base & 511;
    const float bj = b3[n];
    float mm[4] = {0.0f, 0.0f, 0.0f, 0.0f};
    float sum[4] = {0.0f, 0.0f, 0.0f, 0.0f};
    const float4* C3v = reinterpret_cast<const float4*>(g_C3);
#pragma unroll
    for (int t = 0; t < TSTEPS; t++) {
        float4 c = C3v[t * (NM3 / 4) + i4];
        float cv[4] = { c.x, c.y, c.z, c.w };
#pragma unroll
        for (int h = 0; h < 4; h++) {
            float v = cv[h] + bj;
            float m3 = BETA * mm[h] + v;
            float s = (m3 > 1.0f) ? 1.0f : 0.0f;
            mm[h] = m3 - s;
            sum[h] += s;
        }
    }
#pragma unroll
    for (int h = 0; h < 4; h++)
        out[(size_t)(m + h) * L3N + n] = sum[h];
}

// ---------------- host ----------------
extern "C" void kernel_launch(void* const* d_in, const int* in_sizes, int n_in,
                              void* d_out, int out_size)
{
    const float* x  = (const float*)d_in[0];
    const float* W1 = (const float*)d_in[1];
    const float* b1 = (const float*)d_in[2];
    const float* W2 = (const float*)d_in[3];
    const float* b2 = (const float*)d_in[4];
    const float* W3 = (const float*)d_in[5];
    const float* b3 = (const float*)d_in[6];
    float* out = (float*)d_out;

    float *xT, *w1T, *w2T, *w3T, *c1T, *s1, *C2, *C3;
    cudaGetSymbolAddress((void**)&xT,  g_xT);
    cudaGetSymbolAddress((void**)&w1T, g_w1T);
    cudaGetSymbolAddress((void**)&w2T, g_w2T);
    cudaGetSymbolAddress((void**)&w3T, g_w3T);
    cudaGetSymbolAddress((void**)&c1T, g_c1T);
    cudaGetSymbolAddress((void**)&s1,  g_s1);
    cudaGetSymbolAddress((void**)&C2,  g_C2);
    cudaGetSymbolAddress((void**)&C3,  g_C3);

    dim3 tb(32, 8);
    transpose_k<<<dim3(K1IN / 32, MB  / 32), tb>>>(x,  xT,  MB,  K1IN);
    transpose_k<<<dim3(K1IN / 32, L1N / 32), tb>>>(W1, w1T, L1N, K1IN);
    transpose_k<<<dim3(L1N  / 32, L2N / 32), tb>>>(W2, w2T, L2N, L1N);
    transpose_k<<<dim3(L2N  / 32, L3N / 32), tb>>>(W3, w3T, L3N, L2N);

    // layer-1 current, once: c1T = (x @ W1^T + b1)^T   (128 tiles, 1/CTA — as R12)
    gemmB<0><<<128, 256>>>(xT, 0, w1T, L1N, b1, c1T, 0, K1IN, 32, 128);

    // 16-step layer-1 spike trains (separate kernel — as R12)
    sim_layer1<<<NM2 / 256, 256>>>();

    // batched layer-2 GEMM: 2048 tiles, grid 2048, 1 tile/CTA — as R12
    gemmB<1><<<2048, 256>>>(s1, (size_t)NM2, w2T, L2N, nullptr,
                            C2, (size_t)NM2, L1N, 32, 2048);

    // layer-2 membrane recurrence (float4), spikes in-place
    rec2<<<NM2 / 4 / 256, 256>>>(b2);

    // batched layer-3 GEMM: 512 tiles, persistent grid 256 -> exactly 2 tiles/CTA
    gemmB<1><<<256, 256>>>(C2, (size_t)NM2, w3T, L3N, nullptr,
                           C3, (size_t)NM3, L2N, 8, 512);

    // layer-3 recurrence + spike-count sum -> out (float4 loads)
    rec3<<<NM3 / 4 / 256, 256>>>(b3, out);
}